// round 14
// baseline (speedup 1.0000x reference)
#include <cuda_runtime.h>
#include <cuda_bf16.h>
#include <math.h>
#include <stdint.h>

// ---------------------------------------------------------------- shapes
#define N_S 8192
#define M_X 4096
#define D_F 784
#define D_PAD 832              // 13 * 64, zero padded (valid k16 steps: 49)
#define LOG_2PI 1.8378770664093453f

#define BN 128                 // samples per unit (MMA M)
#define BM 128                 // components per unit (MMA N)
#define KSTAGES 13             // 13 k-steps of 64 per unit
#define UNITS_N (N_S / BN)     // 64
#define UNITS_M (M_X / BM)     // 32
#define TOT_UNITS (UNITS_N * UNITS_M)   // 2048
#define GRID 296               // 2 CTAs per SM on 148 SMs
#define NSPLIT (UNITS_M * 2)   // 64 partials per sample row
#define NSTAGE 3

#define A_BYTES (BN * 128)     // 16384 (128 rows x 64 bf16)
#define STG_BYTES (2 * A_BYTES)// 32768 (A + B)
#define SMEM_TOTAL (NSTAGE * STG_BYTES + 1024)   // 97.3KB -> 2 CTAs/SM

#define ROWB (D_PAD * 2)       // bytes per row of bf16 matrix (1664)

// ---------------------------------------------------------------- scratch
__device__ __nv_bfloat16 g_Ubf[(size_t)N_S * D_PAD];
__device__ __nv_bfloat16 g_Vbf[(size_t)M_X * D_PAD];
__device__ float g_usq[N_S];        // |u|^2
__device__ float g_vsqh[M_X];       // 0.5 * |v|^2
__device__ float g_c0;
__device__ float2 g_part[(size_t)NSPLIT * N_S];  // (mx, sm) partials

// ---------------------------------------------------------------- helpers
__device__ __forceinline__ uint32_t smem_u32(const void* p) {
    uint32_t a;
    asm("{ .reg .u64 t; cvta.to.shared.u64 t, %1; cvt.u32.u64 %0, t; }" : "=r"(a) : "l"(p));
    return a;
}
__device__ __forceinline__ void cp_async16(uint32_t dst, const void* src) {
    asm volatile("cp.async.cg.shared.global [%0], [%1], 16;" :: "r"(dst), "l"(src));
}
__device__ __forceinline__ void ldsm_x4(uint32_t* r, uint32_t addr) {
    asm volatile("ldmatrix.sync.aligned.m8n8.x4.shared.b16 {%0,%1,%2,%3}, [%4];"
                 : "=r"(r[0]), "=r"(r[1]), "=r"(r[2]), "=r"(r[3]) : "r"(addr));
}
__device__ __forceinline__ void mma_16816(float* c, const uint32_t* a,
                                          const uint32_t* b) {
    asm volatile(
        "mma.sync.aligned.m16n8k16.row.col.f32.bf16.bf16.f32 "
        "{%0,%1,%2,%3}, {%4,%5,%6,%7}, {%8,%9}, {%0,%1,%2,%3};"
        : "+f"(c[0]), "+f"(c[1]), "+f"(c[2]), "+f"(c[3])
        : "r"(a[0]), "r"(a[1]), "r"(a[2]), "r"(a[3]), "r"(b[0]), "r"(b[1]));
}

// ---------------------------------------------------------------- precompute
// Block = 8 warps = 4 row-pairs; each PAIR is split across 2 warps (one per
// D-half). Fixed 4-iteration unrolled loop with validity predicate so the
// compiler can front-batch all 12 loads (MLP). Padding columns (784..832)
// are never written: they are never read by the main kernel (last k-stage
// reads only cols 768..784) and device globals are zero-initialized anyway.
// Last block computes c0.
#define PRE_BLOCKS ((N_S + M_X) / 8 + 1)
__global__ __launch_bounds__(256) void precompute_kernel(
        const float* __restrict__ samples,
        const float* __restrict__ x,
        const float* __restrict__ stdv) {
    if (blockIdx.x == (N_S + M_X) / 8) {
        __shared__ float red[256];
        int t = threadIdx.x;
        float a = 0.0f;
        for (int d = t; d < D_F; d += 256) a += logf(stdv[d]);
        red[t] = a;
        __syncthreads();
#pragma unroll
        for (int s = 128; s > 0; s >>= 1) {
            if (t < s) red[t] += red[t + s];
            __syncthreads();
        }
        if (t == 0) g_c0 = -0.5f * (float)D_F * LOG_2PI - red[0] - logf((float)M_X);
        return;
    }

    __shared__ float pacc[4][2][2];     // [pair-in-block][row-in-pair][half]

    const int w = threadIdx.x >> 5;
    const int lane = threadIdx.x & 31;
    const int pairb = w >> 1;           // 0..3
    const int half = w & 1;             // D-half

    const int p = blockIdx.x * 4 + pairb;   // global row-pair, 0..6143
    const bool isV = p >= N_S / 2;
    const int row0 = isV ? 2 * p - N_S : 2 * p;

    const float* src = isV ? x : samples;
    __nv_bfloat16* dst = isV ? g_Vbf : g_Ubf;

    const float4* s0 = reinterpret_cast<const float4*>(src + (size_t)row0 * D_F);
    const float4* s1 = reinterpret_cast<const float4*>(src + (size_t)(row0 + 1) * D_F);
    const float4* t4 = reinterpret_cast<const float4*>(stdv);
    __nv_bfloat16* d0 = dst + (size_t)row0 * D_PAD;
    __nv_bfloat16* d1 = d0 + D_PAD;

    const int qbase = half * (D_PAD / 8);   // 0 or 104
    const int qlim = half ? (D_F / 4) : (D_PAD / 8);   // 196 or 104

    float acc0 = 0.0f, acc1 = 0.0f;
#pragma unroll
    for (int it = 0; it < 4; it++) {
        const int q = qbase + lane + it * 32;
        if (q < qlim) {
            float4 v0 = s0[q];
            float4 v1 = s1[q];
            float4 st = t4[q];
            float4 r;
            r.x = 1.0f / st.x; r.y = 1.0f / st.y;
            r.z = 1.0f / st.z; r.w = 1.0f / st.w;
            float4 u0, u1;
            u0.x = v0.x * r.x; u0.y = v0.y * r.y; u0.z = v0.z * r.z; u0.w = v0.w * r.w;
            u1.x = v1.x * r.x; u1.y = v1.y * r.y; u1.z = v1.z * r.z; u1.w = v1.w * r.w;
            acc0 += u0.x * u0.x + u0.y * u0.y + u0.z * u0.z + u0.w * u0.w;
            acc1 += u1.x * u1.x + u1.y * u1.y + u1.z * u1.z + u1.w * u1.w;
            __nv_bfloat162 a0 = __floats2bfloat162_rn(u0.x, u0.y);
            __nv_bfloat162 a1 = __floats2bfloat162_rn(u0.z, u0.w);
            __nv_bfloat162 b0 = __floats2bfloat162_rn(u1.x, u1.y);
            __nv_bfloat162 b1 = __floats2bfloat162_rn(u1.z, u1.w);
            uint2 w0, w1;
            w0.x = *reinterpret_cast<uint32_t*>(&a0);
            w0.y = *reinterpret_cast<uint32_t*>(&a1);
            w1.x = *reinterpret_cast<uint32_t*>(&b0);
            w1.y = *reinterpret_cast<uint32_t*>(&b1);
            *reinterpret_cast<uint2*>(d0 + q * 4) = w0;
            *reinterpret_cast<uint2*>(d1 + q * 4) = w1;
        }
    }
#pragma unroll
    for (int o = 16; o > 0; o >>= 1) {
        acc0 += __shfl_xor_sync(0xffffffffu, acc0, o);
        acc1 += __shfl_xor_sync(0xffffffffu, acc1, o);
    }
    if (lane == 0) {
        pacc[pairb][0][half] = acc0;
        pacc[pairb][1][half] = acc1;
    }
    __syncthreads();
    if (threadIdx.x < 8) {
        int pb = threadIdx.x >> 1, r = threadIdx.x & 1;
        int pp = blockIdx.x * 4 + pb;
        bool iV = pp >= N_S / 2;
        int rr = (iV ? 2 * pp - N_S : 2 * pp) + r;
        float a = pacc[pb][r][0] + pacc[pb][r][1];
        if (iV) g_vsqh[rr] = 0.5f * a;
        else    g_usq[rr] = a;
    }
}

// ---------------------------------------------------------------- main kernel
// Persistent balanced grid: 296 CTAs, unit u = bid + j*296 over 2048 units.
// Last k-stage: only kk=0 computed (cols 784..832 are zero pad) and only
// logical chunks 0..1 are loaded by cp.async (the rest are never read by
// ldsm at kkmax=1 -- logical chunk c is stored at c^(r&7) and read back at
// ch^(r&7), so skipping in logical space is exact).
__global__ __launch_bounds__(256, 2) void gmm_hmma_kernel() {
    extern __shared__ char smem_raw[];
    uint32_t sb_raw = smem_u32(smem_raw);
    uint32_t stg0 = (sb_raw + 1023u) & ~1023u;

    const int tid = threadIdx.x;
    const int lane = tid & 31;
    const int wid = tid >> 5;
    const int warpRow = wid & 3;        // 4 row groups x 32 rows
    const int warpCol = wid >> 2;       // 2 col groups x 64 cols
    const int bid = blockIdx.x;

    const int nUnits = (TOT_UNITS - bid + GRID - 1) / GRID;   // 6 or 7
    const int totS = nUnits * KSTAGES;

    // per-thread constant cp.async offsets (4 chunks of the 1024-chunk tile)
    // logical chunk index within a row is (tid & 7), identical for all i.
    uint32_t swo[4];      // swizzled smem offsets within a 16KB half-stage
    uint32_t gso[4];      // source byte offsets within a 128-row k-slab
#pragma unroll
    for (int i = 0; i < 4; i++) {
        int idx = tid + i * 256;
        int row = idx >> 3;
        int c   = idx & 7;
        swo[i] = (uint32_t)row * 128 + (uint32_t)((c ^ (row & 7)) << 4);
        gso[i] = (uint32_t)row * ROWB + (uint32_t)c * 16;
    }
    const bool tail_thread = (tid & 7) >= 2;   // chunks never read on last stage

    // -------- issuer cursor (2 stages ahead of consumer); incremental pointers
    int is_cnt = 0, is_u = bid, is_ks = 0;
    uint32_t is_dst = stg0;
    const char* pA = (const char*)g_Ubf + (size_t)(bid >> 5) * BN * ROWB;
    const char* pB = (const char*)g_Vbf + (size_t)(bid & 31) * BM * ROWB;

    auto issue_next = [&]() {
        if (is_cnt < totS && !(tail_thread && is_ks == KSTAGES - 1)) {
#pragma unroll
            for (int i = 0; i < 4; i++) {
                cp_async16(is_dst + swo[i], pA + gso[i]);
                cp_async16(is_dst + A_BYTES + swo[i], pB + gso[i]);
            }
        }
        asm volatile("cp.async.commit_group;" ::: "memory");
        is_cnt++;
        is_dst += STG_BYTES;
        if (is_dst == stg0 + NSTAGE * STG_BYTES) is_dst = stg0;
        pA += 128; pB += 128;
        if (++is_ks == KSTAGES) {
            is_ks = 0;
            is_u += GRID;
            pA = (const char*)g_Ubf + (size_t)(is_u >> 5) * BN * ROWB;
            pB = (const char*)g_Vbf + (size_t)(is_u & 31) * BM * ROWB;
        }
    };

    issue_next();
    issue_next();

    // ldmatrix lane-address components (constant per thread)
    const int a_rowl = (lane & 7) + ((lane >> 3) & 1) * 8;  // 0..15
    const int a_csel = lane >> 4;                           // 0/1
    const int b_rowl = (lane & 7) + (lane >> 4) * 8;        // 0..15
    const int b_csel = (lane >> 3) & 1;                     // 0/1

    uint32_t co_base = stg0;
    for (int j = 0; j < nUnits; j++) {
        const int u = bid + j * GRID;
        const int nt = u >> 5, mt = u & 31;
        const int n0 = nt * BN, m0 = mt * BM;

        float acc[2][8][4];
#pragma unroll
        for (int rf = 0; rf < 2; rf++)
#pragma unroll
            for (int cf = 0; cf < 8; cf++)
#pragma unroll
                for (int q = 0; q < 4; q++) acc[rf][cf][q] = 0.0f;

        for (int ks = 0; ks < KSTAGES; ks++) {
            asm volatile("cp.async.wait_group 1;" ::: "memory");
            __syncthreads();
            issue_next();

            uint32_t As = co_base;
            uint32_t Bs = co_base + A_BYTES;
            // ks < 12: all 4 k16 sub-steps; ks == 12: only kk=0 (rest is pad)
            const int kkmax = (ks == KSTAGES - 1) ? 1 : 4;
#pragma unroll
            for (int kk = 0; kk < 4; kk++) {
                if (kk >= kkmax) break;
                uint32_t a[2][4];
#pragma unroll
                for (int rf = 0; rf < 2; rf++) {
                    int r = warpRow * 32 + rf * 16 + a_rowl;
                    int ch = 2 * kk + a_csel;
                    ldsm_x4(a[rf], As + r * 128 + ((ch ^ (r & 7)) << 4));
                }
                uint32_t b[4][4];
#pragma unroll
                for (int cp = 0; cp < 4; cp++) {
                    int r = warpCol * 64 + cp * 16 + b_rowl;
                    int ch = 2 * kk + b_csel;
                    ldsm_x4(b[cp], Bs + r * 128 + ((ch ^ (r & 7)) << 4));
                }
#pragma unroll
                for (int rf = 0; rf < 2; rf++)
#pragma unroll
                    for (int cf = 0; cf < 8; cf++)
                        mma_16816(acc[rf][cf], a[rf], &b[cf >> 1][(cf & 1) * 2]);
            }
            co_base += STG_BYTES;
            if (co_base == stg0 + NSTAGE * STG_BYTES) co_base = stg0;
        }

        // -------- epilogue: online logsumexp for this 128x128 unit,
        // per-warp quad reduce, direct global partial write (no smem, no sync)
        const float* vsm = g_vsqh + m0 + warpCol * 64;
        float pv[16];
        {
            int cbase = (lane & 3) * 2;
#pragma unroll
            for (int cf = 0; cf < 8; cf++) {
                pv[2 * cf]     = vsm[cf * 8 + cbase];
                pv[2 * cf + 1] = vsm[cf * 8 + cbase + 1];
            }
        }
        const int split = mt * 2 + warpCol;
#pragma unroll
        for (int rf = 0; rf < 2; rf++) {
#pragma unroll
            for (int h = 0; h < 2; h++) {
                float v[16];
                float lm = -INFINITY;
#pragma unroll
                for (int cf = 0; cf < 8; cf++) {
                    float v0 = acc[rf][cf][2 * h + 0] - pv[2 * cf];
                    float v1 = acc[rf][cf][2 * h + 1] - pv[2 * cf + 1];
                    v[2 * cf] = v0; v[2 * cf + 1] = v1;
                    lm = fmaxf(lm, fmaxf(v0, v1));
                }
                float ls = 0.f;
#pragma unroll
                for (int jj = 0; jj < 16; jj++) ls += __expf(v[jj] - lm);
                // quad reduce across (lane&3) -> full 64-col coverage
#pragma unroll
                for (int o = 1; o <= 2; o <<= 1) {
                    float m2 = __shfl_xor_sync(0xffffffffu, lm, o);
                    float s2 = __shfl_xor_sync(0xffffffffu, ls, o);
                    float nm = fmaxf(lm, m2);
                    ls = ls * __expf(lm - nm) + s2 * __expf(m2 - nm);
                    lm = nm;
                }
                if ((lane & 3) == 0) {
                    int row = warpRow * 32 + rf * 16 + h * 8 + (lane >> 2);
                    g_part[(size_t)split * N_S + n0 + row] = make_float2(lm, ls);
                }
            }
        }
    }
}

// ---------------------------------------------------------------- finalize
__global__ void finalize_kernel(float* __restrict__ out) {
    int n = blockIdx.x * blockDim.x + threadIdx.x;
    if (n >= N_S) return;
    float m = -INFINITY;
    float2 p[NSPLIT / 8][8];
#pragma unroll
    for (int pb = 0; pb < NSPLIT / 8; pb++)
#pragma unroll
        for (int q = 0; q < 8; q++) {
            p[pb][q] = g_part[(size_t)(pb * 8 + q) * N_S + n];
            m = fmaxf(m, p[pb][q].x);
        }
    float s = 0.f;
#pragma unroll
    for (int pb = 0; pb < NSPLIT / 8; pb++)
#pragma unroll
        for (int q = 0; q < 8; q++)
            s += p[pb][q].y * __expf(p[pb][q].x - m);
    out[n] = g_c0 - g_usq[n] * 0.5f + m + logf(s);
}

// ---------------------------------------------------------------- launch
extern "C" void kernel_launch(void* const* d_in, const int* in_sizes, int n_in,
                              void* d_out, int out_size) {
    const float* samples = (const float*)d_in[0];
    const float* x       = (const float*)d_in[1];
    const float* stdv    = (const float*)d_in[2];
    float* out = (float*)d_out;

    cudaFuncSetAttribute(gmm_hmma_kernel,
                         cudaFuncAttributeMaxDynamicSharedMemorySize, SMEM_TOTAL);

    precompute_kernel<<<PRE_BLOCKS, 256>>>(samples, x, stdv);
    gmm_hmma_kernel<<<GRID, 256, SMEM_TOTAL>>>();
    finalize_kernel<<<(N_S + 255) / 256, 256>>>(out);
}

// round 15
// speedup vs baseline: 1.0165x; 1.0165x over previous
#include <cuda_runtime.h>
#include <cuda_bf16.h>
#include <math.h>
#include <stdint.h>

// ---------------------------------------------------------------- shapes
#define N_S 8192
#define M_X 4096
#define D_F 784
#define D_PAD 832              // 13 * 64, zero padded (valid k16 steps: 49)
#define LOG_2PI 1.8378770664093453f

#define BN 128                 // samples per unit (MMA M)
#define BM 128                 // components per unit (MMA N)
#define KSTAGES 13             // 13 k-steps of 64 per unit
#define UNITS_N (N_S / BN)     // 64
#define UNITS_M (M_X / BM)     // 32
#define TOT_UNITS (UNITS_N * UNITS_M)   // 2048
#define GRID 296               // 2 CTAs per SM on 148 SMs
#define NSPLIT (UNITS_M * 2)   // 64 partials per sample row
#define NSTAGE 3

#define A_BYTES (BN * 128)     // 16384 (128 rows x 64 bf16)
#define STG_BYTES (2 * A_BYTES)// 32768 (A + B)
#define SMEM_TOTAL (NSTAGE * STG_BYTES + 1024)   // 97.3KB -> 2 CTAs/SM

#define ROWB (D_PAD * 2)       // bytes per row of bf16 matrix (1664)

// ---------------------------------------------------------------- scratch
__device__ __nv_bfloat16 g_Ubf[(size_t)N_S * D_PAD];
__device__ __nv_bfloat16 g_Vbf[(size_t)M_X * D_PAD];
__device__ float g_usq[N_S];        // |u|^2
__device__ float g_vsqh[M_X];       // 0.5 * |v|^2
__device__ float g_c0;
__device__ float2 g_part[(size_t)NSPLIT * N_S];  // (mx, sm) partials

// ---------------------------------------------------------------- helpers
__device__ __forceinline__ uint32_t smem_u32(const void* p) {
    uint32_t a;
    asm("{ .reg .u64 t; cvta.to.shared.u64 t, %1; cvt.u32.u64 %0, t; }" : "=r"(a) : "l"(p));
    return a;
}
__device__ __forceinline__ void cp_async16(uint32_t dst, const void* src) {
    asm volatile("cp.async.cg.shared.global [%0], [%1], 16;" :: "r"(dst), "l"(src));
}
__device__ __forceinline__ void ldsm_x4(uint32_t* r, uint32_t addr) {
    asm volatile("ldmatrix.sync.aligned.m8n8.x4.shared.b16 {%0,%1,%2,%3}, [%4];"
                 : "=r"(r[0]), "=r"(r[1]), "=r"(r[2]), "=r"(r[3]) : "r"(addr));
}
__device__ __forceinline__ void mma_16816(float* c, const uint32_t* a,
                                          const uint32_t* b) {
    asm volatile(
        "mma.sync.aligned.m16n8k16.row.col.f32.bf16.bf16.f32 "
        "{%0,%1,%2,%3}, {%4,%5,%6,%7}, {%8,%9}, {%0,%1,%2,%3};"
        : "+f"(c[0]), "+f"(c[1]), "+f"(c[2]), "+f"(c[3])
        : "r"(a[0]), "r"(a[1]), "r"(a[2]), "r"(a[3]), "r"(b[0]), "r"(b[1]));
}
__device__ __forceinline__ void pdl_wait() {
    asm volatile("griddepcontrol.wait;" ::: "memory");
}
__device__ __forceinline__ void pdl_trigger() {
    asm volatile("griddepcontrol.launch_dependents;" ::: "memory");
}

// ---------------------------------------------------------------- precompute
// Block = 8 warps = 4 row-pairs; each PAIR is split across 2 warps (one per
// D-half of 104 float4 chunks). Last block computes c0.  (R13 version.)
#define PRE_BLOCKS ((N_S + M_X) / 8 + 1)
__global__ __launch_bounds__(256) void precompute_kernel(
        const float* __restrict__ samples,
        const float* __restrict__ x,
        const float* __restrict__ stdv) {
    if (blockIdx.x == (N_S + M_X) / 8) {
        __shared__ float red[256];
        int t = threadIdx.x;
        float a = 0.0f;
        for (int d = t; d < D_F; d += 256) a += logf(stdv[d]);
        red[t] = a;
        __syncthreads();
#pragma unroll
        for (int s = 128; s > 0; s >>= 1) {
            if (t < s) red[t] += red[t + s];
            __syncthreads();
        }
        if (t == 0) g_c0 = -0.5f * (float)D_F * LOG_2PI - red[0] - logf((float)M_X);
        return;
    }

    __shared__ float pacc[4][2][2];     // [pair-in-block][row-in-pair][half]

    const int w = threadIdx.x >> 5;
    const int lane = threadIdx.x & 31;
    const int pairb = w >> 1;           // 0..3
    const int half = w & 1;             // D-half

    const int p = blockIdx.x * 4 + pairb;   // global row-pair, 0..6143
    const bool isV = p >= N_S / 2;
    const int row0 = isV ? 2 * p - N_S : 2 * p;

    const float* src = isV ? x : samples;
    __nv_bfloat16* dst = isV ? g_Vbf : g_Ubf;

    const float4* s0 = reinterpret_cast<const float4*>(src + (size_t)row0 * D_F);
    const float4* s1 = reinterpret_cast<const float4*>(src + (size_t)(row0 + 1) * D_F);
    const float4* t4 = reinterpret_cast<const float4*>(stdv);
    __nv_bfloat16* d0 = dst + (size_t)row0 * D_PAD;
    __nv_bfloat16* d1 = d0 + D_PAD;

    const int qbase = half * (D_PAD / 8);   // 0 or 104

    float acc0 = 0.0f, acc1 = 0.0f;
#pragma unroll
    for (int qq = lane; qq < D_PAD / 8; qq += 32) {
        int q = qbase + qq;
        float4 u0 = make_float4(0.f, 0.f, 0.f, 0.f);
        float4 u1 = make_float4(0.f, 0.f, 0.f, 0.f);
        if (q < D_F / 4) {
            float4 v0 = s0[q];
            float4 v1 = s1[q];
            float4 st = t4[q];
            float4 r;
            r.x = 1.0f / st.x; r.y = 1.0f / st.y;
            r.z = 1.0f / st.z; r.w = 1.0f / st.w;
            u0.x = v0.x * r.x; u0.y = v0.y * r.y; u0.z = v0.z * r.z; u0.w = v0.w * r.w;
            u1.x = v1.x * r.x; u1.y = v1.y * r.y; u1.z = v1.z * r.z; u1.w = v1.w * r.w;
            acc0 += u0.x * u0.x + u0.y * u0.y + u0.z * u0.z + u0.w * u0.w;
            acc1 += u1.x * u1.x + u1.y * u1.y + u1.z * u1.z + u1.w * u1.w;
        }
        __nv_bfloat162 a0 = __floats2bfloat162_rn(u0.x, u0.y);
        __nv_bfloat162 a1 = __floats2bfloat162_rn(u0.z, u0.w);
        __nv_bfloat162 b0 = __floats2bfloat162_rn(u1.x, u1.y);
        __nv_bfloat162 b1 = __floats2bfloat162_rn(u1.z, u1.w);
        uint2 w0, w1;
        w0.x = *reinterpret_cast<uint32_t*>(&a0);
        w0.y = *reinterpret_cast<uint32_t*>(&a1);
        w1.x = *reinterpret_cast<uint32_t*>(&b0);
        w1.y = *reinterpret_cast<uint32_t*>(&b1);
        *reinterpret_cast<uint2*>(d0 + q * 4) = w0;
        *reinterpret_cast<uint2*>(d1 + q * 4) = w1;
    }
#pragma unroll
    for (int o = 16; o > 0; o >>= 1) {
        acc0 += __shfl_xor_sync(0xffffffffu, acc0, o);
        acc1 += __shfl_xor_sync(0xffffffffu, acc1, o);
    }
    if (lane == 0) {
        pacc[pairb][0][half] = acc0;
        pacc[pairb][1][half] = acc1;
    }
    __syncthreads();
    if (threadIdx.x < 8) {
        int pb = threadIdx.x >> 1, r = threadIdx.x & 1;
        int pp = blockIdx.x * 4 + pb;
        bool iV = pp >= N_S / 2;
        int rr = (iV ? 2 * pp - N_S : 2 * pp) + r;
        float a = pacc[pb][r][0] + pacc[pb][r][1];
        if (iV) g_vsqh[rr] = 0.5f * a;
        else    g_usq[rr] = a;
    }
}

// ---------------------------------------------------------------- main kernel
// Persistent balanced grid: 296 CTAs, unit u = bid + j*296 over 2048 units.
// PDL: waits on precompute's completion before the first data fetch, and
// triggers the dependent finalize launch at its own end.
__global__ __launch_bounds__(256, 2) void gmm_hmma_kernel() {
    extern __shared__ char smem_raw[];
    uint32_t sb_raw = smem_u32(smem_raw);
    uint32_t stg0 = (sb_raw + 1023u) & ~1023u;

    const int tid = threadIdx.x;
    const int lane = tid & 31;
    const int wid = tid >> 5;
    const int warpRow = wid & 3;        // 4 row groups x 32 rows
    const int warpCol = wid >> 2;       // 2 col groups x 64 cols
    const int bid = blockIdx.x;

    const int nUnits = (TOT_UNITS - bid + GRID - 1) / GRID;   // 6 or 7
    const int totS = nUnits * KSTAGES;

    // per-thread constant cp.async offsets (4 chunks of the 1024-chunk tile)
    uint32_t swo[4];      // swizzled smem offsets within a 16KB half-stage
    uint32_t gso[4];      // source byte offsets within a 128-row k-slab
#pragma unroll
    for (int i = 0; i < 4; i++) {
        int idx = tid + i * 256;
        int row = idx >> 3;
        int c   = idx & 7;
        swo[i] = (uint32_t)row * 128 + (uint32_t)((c ^ (row & 7)) << 4);
        gso[i] = (uint32_t)row * ROWB + (uint32_t)c * 16;
    }
    const bool tail_thread = (tid & 7) >= 2;   // chunks never read on last stage

    // -------- issuer cursor (2 stages ahead of consumer); incremental pointers
    int is_cnt = 0, is_u = bid, is_ks = 0;
    uint32_t is_dst = stg0;
    const char* pA = (const char*)g_Ubf + (size_t)(bid >> 5) * BN * ROWB;
    const char* pB = (const char*)g_Vbf + (size_t)(bid & 31) * BM * ROWB;

    auto issue_next = [&]() {
        if (is_cnt < totS && !(tail_thread && is_ks == KSTAGES - 1)) {
#pragma unroll
            for (int i = 0; i < 4; i++) {
                cp_async16(is_dst + swo[i], pA + gso[i]);
                cp_async16(is_dst + A_BYTES + swo[i], pB + gso[i]);
            }
        }
        asm volatile("cp.async.commit_group;" ::: "memory");
        is_cnt++;
        is_dst += STG_BYTES;
        if (is_dst == stg0 + NSTAGE * STG_BYTES) is_dst = stg0;
        pA += 128; pB += 128;
        if (++is_ks == KSTAGES) {
            is_ks = 0;
            is_u += GRID;
            pA = (const char*)g_Ubf + (size_t)(is_u >> 5) * BN * ROWB;
            pB = (const char*)g_Vbf + (size_t)(is_u & 31) * BM * ROWB;
        }
    };

    // PDL: precompute's writes must be complete before we fetch U/V/vsq.
    pdl_wait();

    issue_next();
    issue_next();

    // ldmatrix lane-address components (constant per thread)
    const int a_rowl = (lane & 7) + ((lane >> 3) & 1) * 8;  // 0..15
    const int a_csel = lane >> 4;                           // 0/1
    const int b_rowl = (lane & 7) + (lane >> 4) * 8;        // 0..15
    const int b_csel = (lane >> 3) & 1;                     // 0/1

    uint32_t co_base = stg0;
    for (int j = 0; j < nUnits; j++) {
        const int u = bid + j * GRID;
        const int nt = u >> 5, mt = u & 31;
        const int n0 = nt * BN, m0 = mt * BM;

        float acc[2][8][4];
#pragma unroll
        for (int rf = 0; rf < 2; rf++)
#pragma unroll
            for (int cf = 0; cf < 8; cf++)
#pragma unroll
                for (int q = 0; q < 4; q++) acc[rf][cf][q] = 0.0f;

        for (int ks = 0; ks < KSTAGES; ks++) {
            asm volatile("cp.async.wait_group 1;" ::: "memory");
            __syncthreads();
            issue_next();

            uint32_t As = co_base;
            uint32_t Bs = co_base + A_BYTES;
            // ks < 12: all 4 k16 sub-steps; ks == 12: only kk=0 (rest is pad)
            const int kkmax = (ks == KSTAGES - 1) ? 1 : 4;
#pragma unroll
            for (int kk = 0; kk < 4; kk++) {
                if (kk >= kkmax) break;
                uint32_t a[2][4];
#pragma unroll
                for (int rf = 0; rf < 2; rf++) {
                    int r = warpRow * 32 + rf * 16 + a_rowl;
                    int ch = 2 * kk + a_csel;
                    ldsm_x4(a[rf], As + r * 128 + ((ch ^ (r & 7)) << 4));
                }
                uint32_t b[4][4];
#pragma unroll
                for (int cp = 0; cp < 4; cp++) {
                    int r = warpCol * 64 + cp * 16 + b_rowl;
                    int ch = 2 * kk + b_csel;
                    ldsm_x4(b[cp], Bs + r * 128 + ((ch ^ (r & 7)) << 4));
                }
#pragma unroll
                for (int rf = 0; rf < 2; rf++)
#pragma unroll
                    for (int cf = 0; cf < 8; cf++)
                        mma_16816(acc[rf][cf], a[rf], &b[cf >> 1][(cf & 1) * 2]);
            }
            co_base += STG_BYTES;
            if (co_base == stg0 + NSTAGE * STG_BYTES) co_base = stg0;
        }

        // -------- epilogue: online logsumexp for this 128x128 unit,
        // per-warp quad reduce, direct global partial write (no smem, no sync)
        const float* vsm = g_vsqh + m0 + warpCol * 64;
        float pv[16];
        {
            int cbase = (lane & 3) * 2;
#pragma unroll
            for (int cf = 0; cf < 8; cf++) {
                pv[2 * cf]     = vsm[cf * 8 + cbase];
                pv[2 * cf + 1] = vsm[cf * 8 + cbase + 1];
            }
        }
        const int split = mt * 2 + warpCol;
#pragma unroll
        for (int rf = 0; rf < 2; rf++) {
#pragma unroll
            for (int h = 0; h < 2; h++) {
                float v[16];
                float lm = -INFINITY;
#pragma unroll
                for (int cf = 0; cf < 8; cf++) {
                    float v0 = acc[rf][cf][2 * h + 0] - pv[2 * cf];
                    float v1 = acc[rf][cf][2 * h + 1] - pv[2 * cf + 1];
                    v[2 * cf] = v0; v[2 * cf + 1] = v1;
                    lm = fmaxf(lm, fmaxf(v0, v1));
                }
                float ls = 0.f;
#pragma unroll
                for (int jj = 0; jj < 16; jj++) ls += __expf(v[jj] - lm);
                // quad reduce across (lane&3) -> full 64-col coverage
#pragma unroll
                for (int o = 1; o <= 2; o <<= 1) {
                    float m2 = __shfl_xor_sync(0xffffffffu, lm, o);
                    float s2 = __shfl_xor_sync(0xffffffffu, ls, o);
                    float nm = fmaxf(lm, m2);
                    ls = ls * __expf(lm - nm) + s2 * __expf(m2 - nm);
                    lm = nm;
                }
                if ((lane & 3) == 0) {
                    int row = warpRow * 32 + rf * 16 + h * 8 + (lane >> 2);
                    g_part[(size_t)split * N_S + n0 + row] = make_float2(lm, ls);
                }
            }
        }
    }

    // all partials for this CTA written; allow finalize's grid to launch
    pdl_trigger();
}

// ---------------------------------------------------------------- finalize
__global__ void finalize_kernel(float* __restrict__ out) {
    // PDL: block until the main grid's g_part writes are visible
    pdl_wait();
    int n = blockIdx.x * blockDim.x + threadIdx.x;
    if (n >= N_S) return;
    float m = -INFINITY;
    float2 p[NSPLIT / 8][8];
#pragma unroll
    for (int pb = 0; pb < NSPLIT / 8; pb++)
#pragma unroll
        for (int q = 0; q < 8; q++) {
            p[pb][q] = g_part[(size_t)(pb * 8 + q) * N_S + n];
            m = fmaxf(m, p[pb][q].x);
        }
    float s = 0.f;
#pragma unroll
    for (int pb = 0; pb < NSPLIT / 8; pb++)
#pragma unroll
        for (int q = 0; q < 8; q++)
            s += p[pb][q].y * __expf(p[pb][q].x - m);
    out[n] = g_c0 - g_usq[n] * 0.5f + m + logf(s);
}

// ---------------------------------------------------------------- launch
extern "C" void kernel_launch(void* const* d_in, const int* in_sizes, int n_in,
                              void* d_out, int out_size) {
    const float* samples = (const float*)d_in[0];
    const float* x       = (const float*)d_in[1];
    const float* stdv    = (const float*)d_in[2];
    float* out = (float*)d_out;

    cudaFuncSetAttribute(gmm_hmma_kernel,
                         cudaFuncAttributeMaxDynamicSharedMemorySize, SMEM_TOTAL);

    precompute_kernel<<<PRE_BLOCKS, 256>>>(samples, x, stdv);

    cudaLaunchAttribute pdl_attr[1];
    pdl_attr[0].id = cudaLaunchAttributeProgrammaticStreamSerialization;
    pdl_attr[0].val.programmaticStreamSerializationAllowed = 1;

    {   // main kernel: PDL-dependent on precompute
        cudaLaunchConfig_t cfg = {};
        cfg.gridDim = dim3(GRID, 1, 1);
        cfg.blockDim = dim3(256, 1, 1);
        cfg.dynamicSmemBytes = SMEM_TOTAL;
        cfg.attrs = pdl_attr;
        cfg.numAttrs = 1;
        cudaLaunchKernelEx(&cfg, gmm_hmma_kernel);
    }
    {   // finalize: PDL-dependent on main kernel
        cudaLaunchConfig_t cfg = {};
        cfg.gridDim = dim3((N_S + 255) / 256, 1, 1);
        cfg.blockDim = dim3(256, 1, 1);
        cfg.attrs = pdl_attr;
        cfg.numAttrs = 1;
        cudaLaunchKernelEx(&cfg, finalize_kernel, out);
    }
}

// round 16
// speedup vs baseline: 1.0359x; 1.0191x over previous
#include <cuda_runtime.h>
#include <cuda_bf16.h>
#include <math.h>
#include <stdint.h>

// ---------------------------------------------------------------- shapes
#define N_S 8192
#define M_X 4096
#define D_F 784
#define D_PAD 832              // 13 * 64, zero padded (valid k16 steps: 49)
#define LOG_2PI 1.8378770664093453f

#define BN 128                 // samples per unit (MMA M)
#define BM 128                 // components per unit (MMA N)
#define KSTAGES 13             // 13 k-steps of 64 per unit
#define UNITS_N (N_S / BN)     // 64
#define UNITS_M (M_X / BM)     // 32
#define TOT_UNITS (UNITS_N * UNITS_M)   // 2048
#define GRID 296               // 2 CTAs per SM on 148 SMs
#define NSPLIT (UNITS_M * 2)   // 64 partials per sample row
#define NSTAGE 3
#define MTHREADS 128           // 4 warps, 2x2 warp grid, 64x64 warp tile

#define A_BYTES (BN * 128)     // 16384 (128 rows x 64 bf16)
#define STG_BYTES (2 * A_BYTES)// 32768 (A + B)
#define SMEM_TOTAL (NSTAGE * STG_BYTES + 1024)   // 97.3KB -> 2 CTAs/SM

#define ROWB (D_PAD * 2)       // bytes per row of bf16 matrix (1664)

// ---------------------------------------------------------------- scratch
__device__ __nv_bfloat16 g_Ubf[(size_t)N_S * D_PAD];
__device__ __nv_bfloat16 g_Vbf[(size_t)M_X * D_PAD];
__device__ float g_usq[N_S];        // |u|^2
__device__ float g_vsqh[M_X];       // 0.5 * |v|^2
__device__ float g_c0;
__device__ float2 g_part[(size_t)NSPLIT * N_S];  // (mx, sm) partials

// ---------------------------------------------------------------- helpers
__device__ __forceinline__ uint32_t smem_u32(const void* p) {
    uint32_t a;
    asm("{ .reg .u64 t; cvta.to.shared.u64 t, %1; cvt.u32.u64 %0, t; }" : "=r"(a) : "l"(p));
    return a;
}
__device__ __forceinline__ void cp_async16(uint32_t dst, const void* src) {
    asm volatile("cp.async.cg.shared.global [%0], [%1], 16;" :: "r"(dst), "l"(src));
}
__device__ __forceinline__ void ldsm_x4(uint32_t* r, uint32_t addr) {
    asm volatile("ldmatrix.sync.aligned.m8n8.x4.shared.b16 {%0,%1,%2,%3}, [%4];"
                 : "=r"(r[0]), "=r"(r[1]), "=r"(r[2]), "=r"(r[3]) : "r"(addr));
}
__device__ __forceinline__ void mma_16816(float* c, const uint32_t* a,
                                          const uint32_t* b) {
    asm volatile(
        "mma.sync.aligned.m16n8k16.row.col.f32.bf16.bf16.f32 "
        "{%0,%1,%2,%3}, {%4,%5,%6,%7}, {%8,%9}, {%0,%1,%2,%3};"
        : "+f"(c[0]), "+f"(c[1]), "+f"(c[2]), "+f"(c[3])
        : "r"(a[0]), "r"(a[1]), "r"(a[2]), "r"(a[3]), "r"(b[0]), "r"(b[1]));
}
__device__ __forceinline__ void pdl_wait() {
    asm volatile("griddepcontrol.wait;" ::: "memory");
}
__device__ __forceinline__ void pdl_trigger() {
    asm volatile("griddepcontrol.launch_dependents;" ::: "memory");
}

// ---------------------------------------------------------------- precompute
// (unchanged R13/R15 version)
#define PRE_BLOCKS ((N_S + M_X) / 8 + 1)
__global__ __launch_bounds__(256) void precompute_kernel(
        const float* __restrict__ samples,
        const float* __restrict__ x,
        const float* __restrict__ stdv) {
    if (blockIdx.x == (N_S + M_X) / 8) {
        __shared__ float red[256];
        int t = threadIdx.x;
        float a = 0.0f;
        for (int d = t; d < D_F; d += 256) a += logf(stdv[d]);
        red[t] = a;
        __syncthreads();
#pragma unroll
        for (int s = 128; s > 0; s >>= 1) {
            if (t < s) red[t] += red[t + s];
            __syncthreads();
        }
        if (t == 0) g_c0 = -0.5f * (float)D_F * LOG_2PI - red[0] - logf((float)M_X);
        return;
    }

    __shared__ float pacc[4][2][2];     // [pair-in-block][row-in-pair][half]

    const int w = threadIdx.x >> 5;
    const int lane = threadIdx.x & 31;
    const int pairb = w >> 1;           // 0..3
    const int half = w & 1;             // D-half

    const int p = blockIdx.x * 4 + pairb;   // global row-pair, 0..6143
    const bool isV = p >= N_S / 2;
    const int row0 = isV ? 2 * p - N_S : 2 * p;

    const float* src = isV ? x : samples;
    __nv_bfloat16* dst = isV ? g_Vbf : g_Ubf;

    const float4* s0 = reinterpret_cast<const float4*>(src + (size_t)row0 * D_F);
    const float4* s1 = reinterpret_cast<const float4*>(src + (size_t)(row0 + 1) * D_F);
    const float4* t4 = reinterpret_cast<const float4*>(stdv);
    __nv_bfloat16* d0 = dst + (size_t)row0 * D_PAD;
    __nv_bfloat16* d1 = d0 + D_PAD;

    const int qbase = half * (D_PAD / 8);   // 0 or 104

    float acc0 = 0.0f, acc1 = 0.0f;
#pragma unroll
    for (int qq = lane; qq < D_PAD / 8; qq += 32) {
        int q = qbase + qq;
        float4 u0 = make_float4(0.f, 0.f, 0.f, 0.f);
        float4 u1 = make_float4(0.f, 0.f, 0.f, 0.f);
        if (q < D_F / 4) {
            float4 v0 = s0[q];
            float4 v1 = s1[q];
            float4 st = t4[q];
            float4 r;
            r.x = 1.0f / st.x; r.y = 1.0f / st.y;
            r.z = 1.0f / st.z; r.w = 1.0f / st.w;
            u0.x = v0.x * r.x; u0.y = v0.y * r.y; u0.z = v0.z * r.z; u0.w = v0.w * r.w;
            u1.x = v1.x * r.x; u1.y = v1.y * r.y; u1.z = v1.z * r.z; u1.w = v1.w * r.w;
            acc0 += u0.x * u0.x + u0.y * u0.y + u0.z * u0.z + u0.w * u0.w;
            acc1 += u1.x * u1.x + u1.y * u1.y + u1.z * u1.z + u1.w * u1.w;
        }
        __nv_bfloat162 a0 = __floats2bfloat162_rn(u0.x, u0.y);
        __nv_bfloat162 a1 = __floats2bfloat162_rn(u0.z, u0.w);
        __nv_bfloat162 b0 = __floats2bfloat162_rn(u1.x, u1.y);
        __nv_bfloat162 b1 = __floats2bfloat162_rn(u1.z, u1.w);
        uint2 w0, w1;
        w0.x = *reinterpret_cast<uint32_t*>(&a0);
        w0.y = *reinterpret_cast<uint32_t*>(&a1);
        w1.x = *reinterpret_cast<uint32_t*>(&b0);
        w1.y = *reinterpret_cast<uint32_t*>(&b1);
        *reinterpret_cast<uint2*>(d0 + q * 4) = w0;
        *reinterpret_cast<uint2*>(d1 + q * 4) = w1;
    }
#pragma unroll
    for (int o = 16; o > 0; o >>= 1) {
        acc0 += __shfl_xor_sync(0xffffffffu, acc0, o);
        acc1 += __shfl_xor_sync(0xffffffffu, acc1, o);
    }
    if (lane == 0) {
        pacc[pairb][0][half] = acc0;
        pacc[pairb][1][half] = acc1;
    }
    __syncthreads();
    if (threadIdx.x < 8) {
        int pb = threadIdx.x >> 1, r = threadIdx.x & 1;
        int pp = blockIdx.x * 4 + pb;
        bool iV = pp >= N_S / 2;
        int rr = (iV ? 2 * pp - N_S : 2 * pp) + r;
        float a = pacc[pb][r][0] + pacc[pb][r][1];
        if (iV) g_vsqh[rr] = 0.5f * a;
        else    g_usq[rr] = a;
    }
}

// ---------------------------------------------------------------- main kernel
// 4 warps (2x2 grid, 64x64 warp tile) -> smem read duplication drops from
// 96KB to 64KB per stage, decoupling the shared crossbar from the tensor
// pipe (reads+writes 96KB = 768cyc << 2048cyc MMA per 2-CTA window).
// Persistent balanced grid: 296 CTAs, unit u = bid + j*296 over 2048 units.
__global__ __launch_bounds__(MTHREADS, 2) void gmm_hmma_kernel() {
    extern __shared__ char smem_raw[];
    uint32_t sb_raw = smem_u32(smem_raw);
    uint32_t stg0 = (sb_raw + 1023u) & ~1023u;

    const int tid = threadIdx.x;
    const int lane = tid & 31;
    const int wid = tid >> 5;
    const int warpRow = wid & 1;        // 2 row groups x 64 rows
    const int warpCol = wid >> 1;       // 2 col groups x 64 cols
    const int bid = blockIdx.x;

    const int nUnits = (TOT_UNITS - bid + GRID - 1) / GRID;   // 6 or 7
    const int totS = nUnits * KSTAGES;

    // per-thread constant cp.async offsets (8 chunks of the 1024-chunk tile)
    // logical chunk index within a row is (tid & 7), identical for all i.
    uint32_t swo[8];      // swizzled smem offsets within a 16KB half-stage
    uint32_t gso[8];      // source byte offsets within a 128-row k-slab
#pragma unroll
    for (int i = 0; i < 8; i++) {
        int idx = tid + i * MTHREADS;
        int row = idx >> 3;
        int c   = idx & 7;
        swo[i] = (uint32_t)row * 128 + (uint32_t)((c ^ (row & 7)) << 4);
        gso[i] = (uint32_t)row * ROWB + (uint32_t)c * 16;
    }
    const bool tail_thread = (tid & 7) >= 2;   // chunks never read on last stage

    // -------- issuer cursor (2 stages ahead of consumer); incremental pointers
    int is_cnt = 0, is_u = bid, is_ks = 0;
    uint32_t is_dst = stg0;
    const char* pA = (const char*)g_Ubf + (size_t)(bid >> 5) * BN * ROWB;
    const char* pB = (const char*)g_Vbf + (size_t)(bid & 31) * BM * ROWB;

    auto issue_next = [&]() {
        if (is_cnt < totS && !(tail_thread && is_ks == KSTAGES - 1)) {
#pragma unroll
            for (int i = 0; i < 8; i++) {
                cp_async16(is_dst + swo[i], pA + gso[i]);
                cp_async16(is_dst + A_BYTES + swo[i], pB + gso[i]);
            }
        }
        asm volatile("cp.async.commit_group;" ::: "memory");
        is_cnt++;
        is_dst += STG_BYTES;
        if (is_dst == stg0 + NSTAGE * STG_BYTES) is_dst = stg0;
        pA += 128; pB += 128;
        if (++is_ks == KSTAGES) {
            is_ks = 0;
            is_u += GRID;
            pA = (const char*)g_Ubf + (size_t)(is_u >> 5) * BN * ROWB;
            pB = (const char*)g_Vbf + (size_t)(is_u & 31) * BM * ROWB;
        }
    };

    // PDL: precompute's writes must be complete before we fetch U/V/vsq.
    pdl_wait();

    issue_next();
    issue_next();

    // ldmatrix lane-address components (constant per thread)
    const int a_rowl = (lane & 7) + ((lane >> 3) & 1) * 8;  // 0..15
    const int a_csel = lane >> 4;                           // 0/1
    const int b_rowl = (lane & 7) + (lane >> 4) * 8;        // 0..15
    const int b_csel = (lane >> 3) & 1;                     // 0/1

    uint32_t co_base = stg0;
    for (int j = 0; j < nUnits; j++) {
        const int u = bid + j * GRID;
        const int nt = u >> 5, mt = u & 31;
        const int n0 = nt * BN, m0 = mt * BM;

        float acc[4][8][4];
#pragma unroll
        for (int rf = 0; rf < 4; rf++)
#pragma unroll
            for (int cf = 0; cf < 8; cf++)
#pragma unroll
                for (int q = 0; q < 4; q++) acc[rf][cf][q] = 0.0f;

        for (int ks = 0; ks < KSTAGES; ks++) {
            asm volatile("cp.async.wait_group 1;" ::: "memory");
            __syncthreads();
            issue_next();

            uint32_t As = co_base;
            uint32_t Bs = co_base + A_BYTES;
            // ks < 12: all 4 k16 sub-steps; ks == 12: only kk=0 (rest is pad)
            const int kkmax = (ks == KSTAGES - 1) ? 1 : 4;
#pragma unroll
            for (int kk = 0; kk < 4; kk++) {
                if (kk >= kkmax) break;
                uint32_t a[4][4];
#pragma unroll
                for (int rf = 0; rf < 4; rf++) {
                    int r = warpRow * 64 + rf * 16 + a_rowl;
                    int ch = 2 * kk + a_csel;
                    ldsm_x4(a[rf], As + r * 128 + ((ch ^ (r & 7)) << 4));
                }
                uint32_t b[4][4];
#pragma unroll
                for (int cp = 0; cp < 4; cp++) {
                    int r = warpCol * 64 + cp * 16 + b_rowl;
                    int ch = 2 * kk + b_csel;
                    ldsm_x4(b[cp], Bs + r * 128 + ((ch ^ (r & 7)) << 4));
                }
#pragma unroll
                for (int rf = 0; rf < 4; rf++)
#pragma unroll
                    for (int cf = 0; cf < 8; cf++)
                        mma_16816(acc[rf][cf], a[rf], &b[cf >> 1][(cf & 1) * 2]);
            }
            co_base += STG_BYTES;
            if (co_base == stg0 + NSTAGE * STG_BYTES) co_base = stg0;
        }

        // -------- epilogue: online logsumexp for this 128x128 unit,
        // per-warp quad reduce, direct global partial write (no smem, no sync)
        const float* vsm = g_vsqh + m0 + warpCol * 64;
        float pv[16];
        {
            int cbase = (lane & 3) * 2;
#pragma unroll
            for (int cf = 0; cf < 8; cf++) {
                pv[2 * cf]     = vsm[cf * 8 + cbase];
                pv[2 * cf + 1] = vsm[cf * 8 + cbase + 1];
            }
        }
        const int split = mt * 2 + warpCol;
#pragma unroll
        for (int rf = 0; rf < 4; rf++) {
#pragma unroll
            for (int h = 0; h < 2; h++) {
                float v[16];
                float lm = -INFINITY;
#pragma unroll
                for (int cf = 0; cf < 8; cf++) {
                    float v0 = acc[rf][cf][2 * h + 0] - pv[2 * cf];
                    float v1 = acc[rf][cf][2 * h + 1] - pv[2 * cf + 1];
                    v[2 * cf] = v0; v[2 * cf + 1] = v1;
                    lm = fmaxf(lm, fmaxf(v0, v1));
                }
                float ls = 0.f;
#pragma unroll
                for (int jj = 0; jj < 16; jj++) ls += __expf(v[jj] - lm);
                // quad reduce across (lane&3) -> full 64-col coverage
#pragma unroll
                for (int o = 1; o <= 2; o <<= 1) {
                    float m2 = __shfl_xor_sync(0xffffffffu, lm, o);
                    float s2 = __shfl_xor_sync(0xffffffffu, ls, o);
                    float nm = fmaxf(lm, m2);
                    ls = ls * __expf(lm - nm) + s2 * __expf(m2 - nm);
                    lm = nm;
                }
                if ((lane & 3) == 0) {
                    int row = warpRow * 64 + rf * 16 + h * 8 + (lane >> 2);
                    g_part[(size_t)split * N_S + n0 + row] = make_float2(lm, ls);
                }
            }
        }
    }

    // all partials for this CTA written; allow finalize's grid to launch
    pdl_trigger();
}

// ---------------------------------------------------------------- finalize
__global__ void finalize_kernel(float* __restrict__ out) {
    // PDL: block until the main grid's g_part writes are visible
    pdl_wait();
    int n = blockIdx.x * blockDim.x + threadIdx.x;
    if (n >= N_S) return;
    float m = -INFINITY;
    float2 p[NSPLIT / 8][8];
#pragma unroll
    for (int pb = 0; pb < NSPLIT / 8; pb++)
#pragma unroll
        for (int q = 0; q < 8; q++) {
            p[pb][q] = g_part[(size_t)(pb * 8 + q) * N_S + n];
            m = fmaxf(m, p[pb][q].x);
        }
    float s = 0.f;
#pragma unroll
    for (int pb = 0; pb < NSPLIT / 8; pb++)
#pragma unroll
        for (int q = 0; q < 8; q++)
            s += p[pb][q].y * __expf(p[pb][q].x - m);
    out[n] = g_c0 - g_usq[n] * 0.5f + m + logf(s);
}

// ---------------------------------------------------------------- launch
extern "C" void kernel_launch(void* const* d_in, const int* in_sizes, int n_in,
                              void* d_out, int out_size) {
    const float* samples = (const float*)d_in[0];
    const float* x       = (const float*)d_in[1];
    const float* stdv    = (const float*)d_in[2];
    float* out = (float*)d_out;

    cudaFuncSetAttribute(gmm_hmma_kernel,
                         cudaFuncAttributeMaxDynamicSharedMemorySize, SMEM_TOTAL);

    precompute_kernel<<<PRE_BLOCKS, 256>>>(samples, x, stdv);

    cudaLaunchAttribute pdl_attr[1];
    pdl_attr[0].id = cudaLaunchAttributeProgrammaticStreamSerialization;
    pdl_attr[0].val.programmaticStreamSerializationAllowed = 1;

    {   // main kernel: PDL-dependent on precompute
        cudaLaunchConfig_t cfg = {};
        cfg.gridDim = dim3(GRID, 1, 1);
        cfg.blockDim = dim3(MTHREADS, 1, 1);
        cfg.dynamicSmemBytes = SMEM_TOTAL;
        cfg.attrs = pdl_attr;
        cfg.numAttrs = 1;
        cudaLaunchKernelEx(&cfg, gmm_hmma_kernel);
    }
    {   // finalize: PDL-dependent on main kernel
        cudaLaunchConfig_t cfg = {};
        cfg.gridDim = dim3((N_S + 255) / 256, 1, 1);
        cfg.blockDim = dim3(256, 1, 1);
        cfg.attrs = pdl_attr;
        cfg.numAttrs = 1;
        cudaLaunchKernelEx(&cfg, finalize_kernel, out);
    }
}